// round 14
// baseline (speedup 1.0000x reference)
#include <cuda_runtime.h>
#include <cstdint>

namespace {

constexpr int Mm = 30;
constexpr int NPAIR = 64 * 512;       // 32768
constexpr int NPAIR2 = NPAIR / 2;     // 16384 pair-pairs
constexpr unsigned FULLM = 0xffffffffu;
constexpr int GSTRIDE = 34;

// emb kernel config
constexpr int WARPS1 = 8;
constexpr int THREADS1 = WARPS1 * 32;  // 256
constexpr int GRID1 = 296;             // 2 blocks/SM

// fit kernel config
constexpr int WARPS2 = 8;
constexpr int THREADS2 = WARPS2 * 32;  // 256
constexpr int GRID2 = 296;             // 2 blocks/SM
constexpr int NTILES = NPAIR / 16;     // 2048 (16 pairs per tile)

struct Smem1 {
  uint4  b1f[8 * 32];       // emb layer1 B-frags (b0h,b1h,b0l,b1l)
  uint4  b2f[8 * 32];
  float4 w0colf4[32];
  float2 bias1f[4 * 32];
  float2 bias2f[4 * 32];
  float  be0s[32];
  __align__(16) float gbuf[WARPS1][1024];
};

struct Smem2 {
  uint4  f0[16 * 8 * 32];   // fit0 B-frags, K-permuted by sigma  64 KB
  uint4  f1[4 * 8 * 32];    // 16 KB
  uint4  f2[4 * 8 * 32];    // 16 KB
  float2 bias0f[8 * 32];
  float2 bias1f[8 * 32];
  float2 bias2f[8 * 32];
  float  wf3s[64];
  float  bf3s;
};

// D scratch in FRAGMENT-MAJOR layout: uint2 Dg2[tile][kt][sub][lane],
// tile=pair/16, kt=0..15, sub=0..3, lane=g*4+q. Entry = (hi,lo) bf16x2 of
// the mma A-fragment element: sub0=(pair g, j=kt*8+q), sub1=(pair g+8, same),
// sub2=(pair g, j+4), sub3=(pair g+8, j+4), where uint2-index j covers
// permuted-K k' = 2j,2j+1 and k' = n*8+k (sigma).
__device__ uint2 Dg2[(size_t)NTILES * 2048];  // 32 MB

// Precomputed fit fragment tables (built by emb blocks 0..15).
__device__ uint4  Gf0[16 * 8 * 32];
__device__ uint4  Gf1[4 * 8 * 32];
__device__ uint4  Gf2[4 * 8 * 32];
__device__ float2 Gb0[8 * 32];
__device__ float2 Gb1[8 * 32];
__device__ float2 Gb2[8 * 32];
__device__ float  Gw3[64];
__device__ float  Gb3;

__host__ __device__ __forceinline__ int sigma(int r) {
  return (r & 7) * 32 + (r >> 3);
}

__device__ __forceinline__ float tanh_fast(float x) {
  float y;
  asm("tanh.approx.f32 %0, %1;" : "=f"(y) : "f"(x));
  return y;
}
__device__ __forceinline__ float sigmoid_fast(float x) {
  return 0.5f * tanh_fast(0.5f * x) + 0.5f;
}
__device__ __forceinline__ float dot4(float4 a, float4 b) {
  return a.x * b.x + a.y * b.y + a.z * b.z + a.w * b.w;
}
__device__ __forceinline__ unsigned bfpack(float keven, float kodd) {
  unsigned r;
  asm("cvt.rn.bf16x2.f32 %0, %1, %2;" : "=r"(r) : "f"(kodd), "f"(keven));
  return r;
}
__device__ __forceinline__ void bfsplit2(float x0, float x1, unsigned& h,
                                         unsigned& l) {
  h = bfpack(x0, x1);
  float h0 = __uint_as_float(h << 16);
  float h1 = __uint_as_float(h & 0xFFFF0000u);
  l = bfpack(x0 - h0, x1 - h1);
}
__device__ __forceinline__ void mma16(float c[4], const unsigned a[4],
                                      unsigned b0, unsigned b1) {
  asm volatile(
      "mma.sync.aligned.m16n8k16.row.col.f32.bf16.bf16.f32 "
      "{%0,%1,%2,%3}, {%4,%5,%6,%7}, {%8,%9}, {%0,%1,%2,%3};"
      : "+f"(c[0]), "+f"(c[1]), "+f"(c[2]), "+f"(c[3])
      : "r"(a[0]), "r"(a[1]), "r"(a[2]), "r"(a[3]), "r"(b0), "r"(b1));
}
__device__ __forceinline__ void mma3(float c[4], const unsigned ah[4],
                                     const unsigned al[4], uint4 bf) {
  mma16(c, ah, bf.x, bf.y);
  mma16(c, al, bf.x, bf.y);
  mma16(c, ah, bf.z, bf.w);
}
__device__ __forceinline__ void c2a_pack(const float ce[4], const float co[4],
                                         unsigned ah[4], unsigned al[4]) {
  bfsplit2(ce[0], ce[1], ah[0], al[0]);
  bfsplit2(ce[2], ce[3], ah[1], al[1]);
  bfsplit2(co[0], co[1], ah[2], al[2]);
  bfsplit2(co[2], co[3], ah[3], al[3]);
}

}  // namespace

// ======================= Kernel 1: emb MLP + bilinear -> D =================

__global__ void __launch_bounds__(THREADS1, 2) emb_kernel(
    const float* __restrict__ Sg, const float* __restrict__ R,
    const float* __restrict__ We0, const float* __restrict__ be0,
    const float* __restrict__ We1, const float* __restrict__ be1,
    const float* __restrict__ We2, const float* __restrict__ be2,
    const float* __restrict__ Wf0, const float* __restrict__ bf0,
    const float* __restrict__ Wf1, const float* __restrict__ bf1,
    const float* __restrict__ Wf2, const float* __restrict__ bf2,
    const float* __restrict__ Wf3, const float* __restrict__ bf3) {
  extern __shared__ char smraw[];
  Smem1* s = reinterpret_cast<Smem1*>(smraw);
  const int tid = threadIdx.x;

  // ---- one-shot fit fragment-table build, distributed over blocks 0..15
  if (blockIdx.x < 16) {
    {
      int i = blockIdx.x * 256 + tid;  // Gf0: 4096 entries
      int L = i & 31, nt = (i >> 5) & 7, kt = i >> 8;
      int q = L & 3, g = L >> 2;
      int r00 = kt * 16 + 2 * q, r10 = r00 + 8;
      int c = nt * 8 + g;
      unsigned b0h, b0l, b1h, b1l;
      bfsplit2(Wf0[sigma(r00) * 64 + c], Wf0[sigma(r00 + 1) * 64 + c], b0h,
               b0l);
      bfsplit2(Wf0[sigma(r10) * 64 + c], Wf0[sigma(r10 + 1) * 64 + c], b1h,
               b1l);
      Gf0[i] = make_uint4(b0h, b1h, b0l, b1l);
    }
    if (tid < 64) {
      int i = blockIdx.x * 64 + tid;  // Gf1/Gf2: 1024 entries
      int L = i & 31, nt = (i >> 5) & 7, kt = i >> 8;
      int q = L & 3, g = L >> 2;
      int r00 = kt * 16 + 2 * q, r10 = r00 + 8;
      int c = nt * 8 + g;
      unsigned b0h, b0l, b1h, b1l;
      bfsplit2(Wf1[r00 * 64 + c], Wf1[(r00 + 1) * 64 + c], b0h, b0l);
      bfsplit2(Wf1[r10 * 64 + c], Wf1[(r10 + 1) * 64 + c], b1h, b1l);
      Gf1[i] = make_uint4(b0h, b1h, b0l, b1l);
      bfsplit2(Wf2[r00 * 64 + c], Wf2[(r00 + 1) * 64 + c], b0h, b0l);
      bfsplit2(Wf2[r10 * 64 + c], Wf2[(r10 + 1) * 64 + c], b1h, b1l);
      Gf2[i] = make_uint4(b0h, b1h, b0l, b1l);
    }
    if (tid < 16) {
      int i = blockIdx.x * 16 + tid;  // biases: 256 entries
      int nt = i >> 5, q = i & 3;
      Gb0[i] = make_float2(bf0[nt * 8 + 2 * q], bf0[nt * 8 + 2 * q + 1]);
      Gb1[i] = make_float2(bf1[nt * 8 + 2 * q], bf1[nt * 8 + 2 * q + 1]);
      Gb2[i] = make_float2(bf2[nt * 8 + 2 * q], bf2[nt * 8 + 2 * q + 1]);
    }
    if (blockIdx.x == 0) {
      if (tid < 64) Gw3[tid] = Wf3[tid];
      if (tid == 0) Gb3 = bf3[0];
    }
  }

  for (int i = tid; i < 256; i += THREADS1) {
    int L = i & 31, nt = (i >> 5) & 3, u = i >> 7;
    int q = L & 3, g = L >> 2;
    int r00 = u * 16 + 2 * q, r10 = r00 + 8;
    int c = nt * 8 + g;
    unsigned b0h, b0l, b1h, b1l;
    bfsplit2(We1[r00 * 32 + c], We1[(r00 + 1) * 32 + c], b0h, b0l);
    bfsplit2(We1[r10 * 32 + c], We1[(r10 + 1) * 32 + c], b1h, b1l);
    s->b1f[i] = make_uint4(b0h, b1h, b0l, b1l);
    bfsplit2(We2[r00 * 32 + c], We2[(r00 + 1) * 32 + c], b0h, b0l);
    bfsplit2(We2[r10 * 32 + c], We2[(r10 + 1) * 32 + c], b1h, b1l);
    s->b2f[i] = make_uint4(b0h, b1h, b0l, b1l);
  }
  for (int i = tid; i < 128; i += THREADS1) {
    int t = i >> 5, L = i & 31, q = L & 3;
    s->bias1f[i] = make_float2(be1[t * 8 + 2 * q], be1[t * 8 + 2 * q + 1]);
    s->bias2f[i] = make_float2(be2[t * 8 + 2 * q], be2[t * 8 + 2 * q + 1]);
  }
  if (tid < 32) {
    s->w0colf4[tid] =
        make_float4(We0[tid], We0[32 + tid], We0[64 + tid], We0[96 + tid]);
    s->be0s[tid] = be0[tid];
  }
  __syncthreads();

  const int lane = tid & 31, wid = tid >> 5;
  const int q = lane & 3, g = lane >> 2;

  float* const gbuf = s->gbuf[wid];
  const float4* const Sg4 = reinterpret_cast<const float4*>(Sg);
  const float4* const R4 = reinterpret_cast<const float4*>(R);

  for (int it = blockIdx.x * WARPS1 + wid; it < NPAIR2; it += GRID1 * WARPS1) {
    const int pair0 = it * 2;
    float bm[2][4] = {{0.f, 0.f, 0.f, 0.f}, {0.f, 0.f, 0.f, 0.f}};

#pragma unroll 1
    for (int pp = 0; pp < 2; pp++) {
      const float4* const sgb = Sg4 + (pair0 + pp) * Mm;

      unsigned a1h[2][2][4], a1l[2][2][4];
#pragma unroll
      for (int mt = 0; mt < 2; mt++) {
        int rA = mt * 16 + g;
        int rB = rA + 8;
        float4 sgA = sgb[rA];
        float4 sgB = (rB < Mm) ? sgb[rB] : make_float4(0.f, 0.f, 0.f, 0.f);
#pragma unroll
        for (int u = 0; u < 2; u++) {
          int c0 = u * 16 + 2 * q;
          int c2 = c0 + 8;
          float4 w0v = s->w0colf4[c0];
          float4 w1v = s->w0colf4[c0 + 1];
          float4 w2v = s->w0colf4[c2];
          float4 w3v = s->w0colf4[c2 + 1];
          float b0v = s->be0s[c0], b1v = s->be0s[c0 + 1];
          float b2v = s->be0s[c2], b3v = s->be0s[c2 + 1];
          bfsplit2(sigmoid_fast(b0v + dot4(sgA, w0v)),
                   sigmoid_fast(b1v + dot4(sgA, w1v)), a1h[mt][u][0],
                   a1l[mt][u][0]);
          bfsplit2(sigmoid_fast(b0v + dot4(sgB, w0v)),
                   sigmoid_fast(b1v + dot4(sgB, w1v)), a1h[mt][u][1],
                   a1l[mt][u][1]);
          bfsplit2(sigmoid_fast(b2v + dot4(sgA, w2v)),
                   sigmoid_fast(b3v + dot4(sgA, w3v)), a1h[mt][u][2],
                   a1l[mt][u][2]);
          bfsplit2(sigmoid_fast(b2v + dot4(sgB, w2v)),
                   sigmoid_fast(b3v + dot4(sgB, w3v)), a1h[mt][u][3],
                   a1l[mt][u][3]);
        }
      }

      float c1v[2][4][4];
#pragma unroll
      for (int nt = 0; nt < 4; nt++) {
        float2 bi = s->bias1f[nt * 32 + lane];
#pragma unroll
        for (int mt = 0; mt < 2; mt++) {
          c1v[mt][nt][0] = bi.x;
          c1v[mt][nt][1] = bi.y;
          c1v[mt][nt][2] = bi.x;
          c1v[mt][nt][3] = bi.y;
        }
#pragma unroll
        for (int u = 0; u < 2; u++) {
          uint4 bf = s->b1f[(u * 4 + nt) * 32 + lane];
#pragma unroll
          for (int mt = 0; mt < 2; mt++)
            mma3(c1v[mt][nt], a1h[mt][u], a1l[mt][u], bf);
        }
      }

      unsigned a2h[2][2][4], a2l[2][2][4];
#pragma unroll
      for (int mt = 0; mt < 2; mt++) {
#pragma unroll
        for (int nt = 0; nt < 4; nt++)
#pragma unroll
          for (int j = 0; j < 4; j++)
            c1v[mt][nt][j] = tanh_fast(c1v[mt][nt][j]);
#pragma unroll
        for (int u = 0; u < 2; u++)
          c2a_pack(c1v[mt][2 * u], c1v[mt][2 * u + 1], a2h[mt][u], a2l[mt][u]);
      }

      float c2v[2][4][4];
#pragma unroll
      for (int nt = 0; nt < 4; nt++) {
        float2 bi = s->bias2f[nt * 32 + lane];
#pragma unroll
        for (int mt = 0; mt < 2; mt++) {
          c2v[mt][nt][0] = bi.x;
          c2v[mt][nt][1] = bi.y;
          c2v[mt][nt][2] = bi.x;
          c2v[mt][nt][3] = bi.y;
        }
#pragma unroll
        for (int u = 0; u < 2; u++) {
          uint4 bf = s->b2f[(u * 4 + nt) * 32 + lane];
#pragma unroll
          for (int mt = 0; mt < 2; mt++)
            mma3(c2v[mt][nt], a2h[mt][u], a2l[mt][u], bf);
        }
      }

#pragma unroll
      for (int mt = 0; mt < 2; mt++) {
#pragma unroll
        for (int nt = 0; nt < 4; nt++) {
          int colb = nt * 8 + 2 * q;
          int r0r = mt * 16 + g;
          *reinterpret_cast<float2*>(&gbuf[r0r * GSTRIDE + colb]) =
              make_float2(c2v[mt][nt][0], c2v[mt][nt][1]);
          int r1r = r0r + 8;
          if (r1r < Mm)
            *reinterpret_cast<float2*>(&gbuf[r1r * GSTRIDE + colb]) =
                make_float2(c2v[mt][nt][2], c2v[mt][nt][3]);
        }
      }
      __syncwarp();
      const float4* const rb = R4 + (pair0 + pp) * Mm;
#pragma unroll 6
      for (int m = 0; m < Mm; m++) {
        float gv = gbuf[m * GSTRIDE + lane];
        float4 r = rb[m];
        bm[pp][0] += r.x * gv;
        bm[pp][1] += r.y * gv;
        bm[pp][2] += r.z * gv;
        bm[pp][3] += r.w * gv;
      }
      __syncwarp();
    }

    // D[k][n] = sum_l Bm[l][k]*Bm[l][n]; store straight into the
    // fragment-major layout fit0 consumes.
#pragma unroll
    for (int pp = 0; pp < 2; pp++) {
      const int P = pair0 + pp;
      float d[8];
#pragma unroll
      for (int k = 0; k < 8; k++) {
        float dv = 0.f;
#pragma unroll
        for (int l = 0; l < 4; l++) {
          float a = __shfl_sync(FULLM, bm[pp][l], k);
          dv += a * bm[pp][l];
        }
        d[k] = dv;
      }
      unsigned h[4], lo[4];
#pragma unroll
      for (int t2 = 0; t2 < 4; t2++)
        bfsplit2(d[2 * t2], d[2 * t2 + 1], h[t2], lo[t2]);
      const int p = P & 15;
      const size_t off = (size_t)(P >> 4) * 2048 + (lane >> 1) * 128 +
                         (((lane & 1) * 2 + (p >> 3)) * 32) + (p & 7) * 4;
      uint4* dst = reinterpret_cast<uint4*>(Dg2 + off);
      dst[0] = make_uint4(h[0], lo[0], h[1], lo[1]);
      dst[1] = make_uint4(h[2], lo[2], h[3], lo[3]);
    }
  }
}

// ======================= Kernel 2: fit MLP (coalesced fragment loads) ======

__global__ void __launch_bounds__(THREADS2, 2) fit_kernel(
    float* __restrict__ out) {
  extern __shared__ char smraw[];
  Smem2* s = reinterpret_cast<Smem2*>(smraw);
  const int tid = threadIdx.x;

  for (int i = tid; i < 16 * 8 * 32; i += THREADS2) s->f0[i] = Gf0[i];
  for (int i = tid; i < 4 * 8 * 32; i += THREADS2) {
    s->f1[i] = Gf1[i];
    s->f2[i] = Gf2[i];
  }
  for (int i = tid; i < 256; i += THREADS2) {
    s->bias0f[i] = Gb0[i];
    s->bias1f[i] = Gb1[i];
    s->bias2f[i] = Gb2[i];
  }
  if (tid < 64) s->wf3s[tid] = Gw3[tid];
  if (tid == 0) s->bf3s = Gb3;
  __syncthreads();

  const int lane = tid & 31, wid = tid >> 5;
  const int q = lane & 3;

  for (int t = blockIdx.x * WARPS2 + wid; t < NTILES; t += GRID2 * WARPS2) {
    const uint2* const tb = Dg2 + (size_t)t * 2048;

    // ---- fit0: A fragments loaded with fully-coalesced 256B LDG.64s
    float c0[8][4];
#pragma unroll
    for (int nt = 0; nt < 8; nt++) {
      float2 bi = s->bias0f[nt * 32 + lane];
      c0[nt][0] = bi.x;
      c0[nt][1] = bi.y;
      c0[nt][2] = bi.x;
      c0[nt][3] = bi.y;
    }
#pragma unroll 4
    for (int kt = 0; kt < 16; kt++) {
      uint2 w0 = tb[kt * 128 + lane];
      uint2 w1 = tb[kt * 128 + 32 + lane];
      uint2 w2 = tb[kt * 128 + 64 + lane];
      uint2 w3 = tb[kt * 128 + 96 + lane];
      unsigned ah[4] = {w0.x, w1.x, w2.x, w3.x};
      unsigned al[4] = {w0.y, w1.y, w2.y, w3.y};
#pragma unroll
      for (int nt = 0; nt < 8; nt++)
        mma3(c0[nt], ah, al, s->f0[(kt * 8 + nt) * 32 + lane]);
    }
    unsigned ah1[4][4], al1[4][4];
#pragma unroll
    for (int nt = 0; nt < 8; nt++)
#pragma unroll
      for (int j = 0; j < 4; j++) c0[nt][j] = tanh_fast(c0[nt][j]);
#pragma unroll
    for (int u = 0; u < 4; u++)
      c2a_pack(c0[2 * u], c0[2 * u + 1], ah1[u], al1[u]);

    float c1[8][4];
#pragma unroll
    for (int nt = 0; nt < 8; nt++) {
      float2 bi = s->bias1f[nt * 32 + lane];
      c1[nt][0] = bi.x;
      c1[nt][1] = bi.y;
      c1[nt][2] = bi.x;
      c1[nt][3] = bi.y;
    }
#pragma unroll 2
    for (int kt = 0; kt < 4; kt++)
#pragma unroll
      for (int nt = 0; nt < 8; nt++)
        mma3(c1[nt], ah1[kt], al1[kt], s->f1[(kt * 8 + nt) * 32 + lane]);
#pragma unroll
    for (int nt = 0; nt < 8; nt++)
#pragma unroll
      for (int j = 0; j < 4; j++) c1[nt][j] = sigmoid_fast(c1[nt][j]);
#pragma unroll
    for (int u = 0; u < 4; u++)
      c2a_pack(c1[2 * u], c1[2 * u + 1], ah1[u], al1[u]);

    float c2[8][4];
#pragma unroll
    for (int nt = 0; nt < 8; nt++) {
      float2 bi = s->bias2f[nt * 32 + lane];
      c2[nt][0] = bi.x;
      c2[nt][1] = bi.y;
      c2[nt][2] = bi.x;
      c2[nt][3] = bi.y;
    }
#pragma unroll 2
    for (int kt = 0; kt < 4; kt++)
#pragma unroll
      for (int nt = 0; nt < 8; nt++)
        mma3(c2[nt], ah1[kt], al1[kt], s->f2[(kt * 8 + nt) * 32 + lane]);

    float slo = 0.f, shi = 0.f;
#pragma unroll
    for (int nt = 0; nt < 8; nt++) {
      float wa = s->wf3s[nt * 8 + 2 * q];
      float wb = s->wf3s[nt * 8 + 2 * q + 1];
      slo += tanh_fast(c2[nt][0]) * wa + tanh_fast(c2[nt][1]) * wb;
      shi += tanh_fast(c2[nt][2]) * wa + tanh_fast(c2[nt][3]) * wb;
    }
    float tot = slo + shi;
#pragma unroll
    for (int off = 16; off; off >>= 1) tot += __shfl_xor_sync(FULLM, tot, off);
    if (lane == 0) {
      atomicAdd(out + (t >> 5), (tot + 16.0f * s->bf3s) * (1.0f / 512.0f));
    }
  }
}

extern "C" void kernel_launch(void* const* d_in, const int* in_sizes, int n_in,
                              void* d_out, int out_size) {
  const float* Sg = (const float*)d_in[0];
  const float* R = (const float*)d_in[1];
  const float* We0 = (const float*)d_in[2];
  const float* be0 = (const float*)d_in[3];
  const float* We1 = (const float*)d_in[4];
  const float* be1 = (const float*)d_in[5];
  const float* We2 = (const float*)d_in[6];
  const float* be2 = (const float*)d_in[7];
  const float* Wf0 = (const float*)d_in[8];
  const float* bf0 = (const float*)d_in[9];
  const float* Wf1 = (const float*)d_in[10];
  const float* bf1 = (const float*)d_in[11];
  const float* Wf2 = (const float*)d_in[12];
  const float* bf2 = (const float*)d_in[13];
  const float* Wf3 = (const float*)d_in[14];
  const float* bf3 = (const float*)d_in[15];
  float* out = (float*)d_out;

  (void)in_sizes;
  (void)n_in;

  cudaFuncSetAttribute(emb_kernel, cudaFuncAttributeMaxDynamicSharedMemorySize,
                       (int)sizeof(Smem1));
  cudaFuncSetAttribute(fit_kernel, cudaFuncAttributeMaxDynamicSharedMemorySize,
                       (int)sizeof(Smem2));

  cudaMemsetAsync(out, 0, (size_t)out_size * sizeof(float));

  emb_kernel<<<GRID1, THREADS1, sizeof(Smem1)>>>(
      Sg, R, We0, be0, We1, be1, We2, be2, Wf0, bf0, Wf1, bf1, Wf2, bf2, Wf3,
      bf3);
  fit_kernel<<<GRID2, THREADS2, sizeof(Smem2)>>>(out);
}

// round 15
// speedup vs baseline: 1.0204x; 1.0204x over previous
#include <cuda_runtime.h>
#include <cstdint>

namespace {

constexpr int Mm = 30;
constexpr int NPAIR = 64 * 512;       // 32768
constexpr int NPAIR2 = NPAIR / 2;     // 16384 pair-pairs
constexpr unsigned FULLM = 0xffffffffu;
constexpr int GSTRIDE = 34;

// emb kernel config
constexpr int WARPS1 = 8;
constexpr int THREADS1 = WARPS1 * 32;  // 256
constexpr int GRID1 = 296;             // 2 blocks/SM

// fit kernel config
constexpr int WARPS2 = 8;
constexpr int THREADS2 = WARPS2 * 32;  // 256
constexpr int GRID2 = 296;             // 2 blocks/SM
constexpr int NTILES = NPAIR / 16;     // 2048 (16 pairs per tile)

struct Smem1 {
  uint4  b1f[8 * 32];       // emb layer1 B-frags (b0h,b1h,b0l,b1l)
  uint4  b2f[8 * 32];
  float4 w0colf4[32];
  float2 bias1f[4 * 32];
  float2 bias2f[4 * 32];
  float  be0s[32];
  __align__(16) float gbuf[WARPS1][1024];
};

struct Smem2 {
  uint4  f0[16 * 8 * 32];   // fit0 B-frags, K-permuted by sigma  64 KB
  uint4  f1[4 * 8 * 32];    // 16 KB
  uint4  f2[4 * 8 * 32];    // 16 KB
  float2 bias0f[8 * 32];
  float2 bias1f[8 * 32];
  float2 bias2f[8 * 32];
  float  wf3s[64];
  float  bf3s;
};

// D scratch, pre-split bf16 hi/lo, K-permuted (R9/R13 layout): uint2 j =
// (hi,lo) bf16x2 of k' = 2j,2j+1 where k' = n*8 + k (sigma permutation).
__device__ uint2 Dg2[(size_t)NPAIR * 128];  // 32 MB

// Precomputed fit fragment tables (built once by setup_kernel).
__device__ uint4  Gf0[16 * 8 * 32];
__device__ uint4  Gf1[4 * 8 * 32];
__device__ uint4  Gf2[4 * 8 * 32];
__device__ float2 Gb0[8 * 32];
__device__ float2 Gb1[8 * 32];
__device__ float2 Gb2[8 * 32];
__device__ float  Gw3[64];
__device__ float  Gb3;

__host__ __device__ __forceinline__ int sigma(int r) {
  return (r & 7) * 32 + (r >> 3);
}

__device__ __forceinline__ float tanh_fast(float x) {
  float y;
  asm("tanh.approx.f32 %0, %1;" : "=f"(y) : "f"(x));
  return y;
}
__device__ __forceinline__ float sigmoid_fast(float x) {
  return 0.5f * tanh_fast(0.5f * x) + 0.5f;
}
__device__ __forceinline__ float dot4(float4 a, float4 b) {
  return a.x * b.x + a.y * b.y + a.z * b.z + a.w * b.w;
}
__device__ __forceinline__ unsigned bfpack(float keven, float kodd) {
  unsigned r;
  asm("cvt.rn.bf16x2.f32 %0, %1, %2;" : "=r"(r) : "f"(kodd), "f"(keven));
  return r;
}
__device__ __forceinline__ void bfsplit2(float x0, float x1, unsigned& h,
                                         unsigned& l) {
  h = bfpack(x0, x1);
  float h0 = __uint_as_float(h << 16);
  float h1 = __uint_as_float(h & 0xFFFF0000u);
  l = bfpack(x0 - h0, x1 - h1);
}
__device__ __forceinline__ void mma16(float c[4], const unsigned a[4],
                                      unsigned b0, unsigned b1) {
  asm volatile(
      "mma.sync.aligned.m16n8k16.row.col.f32.bf16.bf16.f32 "
      "{%0,%1,%2,%3}, {%4,%5,%6,%7}, {%8,%9}, {%0,%1,%2,%3};"
      : "+f"(c[0]), "+f"(c[1]), "+f"(c[2]), "+f"(c[3])
      : "r"(a[0]), "r"(a[1]), "r"(a[2]), "r"(a[3]), "r"(b0), "r"(b1));
}
__device__ __forceinline__ void mma3(float c[4], const unsigned ah[4],
                                     const unsigned al[4], uint4 bf) {
  mma16(c, ah, bf.x, bf.y);
  mma16(c, al, bf.x, bf.y);
  mma16(c, ah, bf.z, bf.w);
}
__device__ __forceinline__ void c2a_pack(const float ce[4], const float co[4],
                                         unsigned ah[4], unsigned al[4]) {
  bfsplit2(ce[0], ce[1], ah[0], al[0]);
  bfsplit2(ce[2], ce[3], ah[1], al[1]);
  bfsplit2(co[0], co[1], ah[2], al[2]);
  bfsplit2(co[2], co[3], ah[3], al[3]);
}

}  // namespace

// ======================= Kernel 0: one-shot fragment-table build ===========
// Widened to 64 blocks x 128 threads (R13's 16x256 was latency-starved).

__global__ void setup_kernel(const float* __restrict__ Wf0,
                             const float* __restrict__ bf0,
                             const float* __restrict__ Wf1,
                             const float* __restrict__ bf1,
                             const float* __restrict__ Wf2,
                             const float* __restrict__ bf2,
                             const float* __restrict__ Wf3,
                             const float* __restrict__ bf3) {
  const int gt = blockIdx.x * blockDim.x + threadIdx.x;
  const int nthr = gridDim.x * blockDim.x;
  for (int i = gt; i < 16 * 8 * 32; i += nthr) {
    int L = i & 31, nt = (i >> 5) & 7, kt = i >> 8;
    int q = L & 3, g = L >> 2;
    int r00 = kt * 16 + 2 * q, r10 = r00 + 8;
    int c = nt * 8 + g;
    unsigned b0h, b0l, b1h, b1l;
    bfsplit2(Wf0[sigma(r00) * 64 + c], Wf0[sigma(r00 + 1) * 64 + c], b0h, b0l);
    bfsplit2(Wf0[sigma(r10) * 64 + c], Wf0[sigma(r10 + 1) * 64 + c], b1h, b1l);
    Gf0[i] = make_uint4(b0h, b1h, b0l, b1l);
  }
  for (int i = gt; i < 4 * 8 * 32; i += nthr) {
    int L = i & 31, nt = (i >> 5) & 7, kt = i >> 8;
    int q = L & 3, g = L >> 2;
    int r00 = kt * 16 + 2 * q, r10 = r00 + 8;
    int c = nt * 8 + g;
    unsigned b0h, b0l, b1h, b1l;
    bfsplit2(Wf1[r00 * 64 + c], Wf1[(r00 + 1) * 64 + c], b0h, b0l);
    bfsplit2(Wf1[r10 * 64 + c], Wf1[(r10 + 1) * 64 + c], b1h, b1l);
    Gf1[i] = make_uint4(b0h, b1h, b0l, b1l);
    bfsplit2(Wf2[r00 * 64 + c], Wf2[(r00 + 1) * 64 + c], b0h, b0l);
    bfsplit2(Wf2[r10 * 64 + c], Wf2[(r10 + 1) * 64 + c], b1h, b1l);
    Gf2[i] = make_uint4(b0h, b1h, b0l, b1l);
  }
  for (int i = gt; i < 256; i += nthr) {
    int nt = i >> 5, q = i & 3;
    Gb0[i] = make_float2(bf0[nt * 8 + 2 * q], bf0[nt * 8 + 2 * q + 1]);
    Gb1[i] = make_float2(bf1[nt * 8 + 2 * q], bf1[nt * 8 + 2 * q + 1]);
    Gb2[i] = make_float2(bf2[nt * 8 + 2 * q], bf2[nt * 8 + 2 * q + 1]);
  }
  if (gt < 64) Gw3[gt] = Wf3[gt];
  if (gt == 0) Gb3 = bf3[0];
}

// ======================= Kernel 1: emb MLP + bilinear -> D =================
// (exact R13/R12 winner)

__global__ void __launch_bounds__(THREADS1, 2) emb_kernel(
    const float* __restrict__ Sg, const float* __restrict__ R,
    const float* __restrict__ We0, const float* __restrict__ be0,
    const float* __restrict__ We1, const float* __restrict__ be1,
    const float* __restrict__ We2, const float* __restrict__ be2) {
  extern __shared__ char smraw[];
  Smem1* s = reinterpret_cast<Smem1*>(smraw);
  const int tid = threadIdx.x;

  for (int i = tid; i < 256; i += THREADS1) {
    int L = i & 31, nt = (i >> 5) & 3, u = i >> 7;
    int q = L & 3, g = L >> 2;
    int r00 = u * 16 + 2 * q, r10 = r00 + 8;
    int c = nt * 8 + g;
    unsigned b0h, b0l, b1h, b1l;
    bfsplit2(We1[r00 * 32 + c], We1[(r00 + 1) * 32 + c], b0h, b0l);
    bfsplit2(We1[r10 * 32 + c], We1[(r10 + 1) * 32 + c], b1h, b1l);
    s->b1f[i] = make_uint4(b0h, b1h, b0l, b1l);
    bfsplit2(We2[r00 * 32 + c], We2[(r00 + 1) * 32 + c], b0h, b0l);
    bfsplit2(We2[r10 * 32 + c], We2[(r10 + 1) * 32 + c], b1h, b1l);
    s->b2f[i] = make_uint4(b0h, b1h, b0l, b1l);
  }
  for (int i = tid; i < 128; i += THREADS1) {
    int t = i >> 5, L = i & 31, q = L & 3;
    s->bias1f[i] = make_float2(be1[t * 8 + 2 * q], be1[t * 8 + 2 * q + 1]);
    s->bias2f[i] = make_float2(be2[t * 8 + 2 * q], be2[t * 8 + 2 * q + 1]);
  }
  if (tid < 32) {
    s->w0colf4[tid] =
        make_float4(We0[tid], We0[32 + tid], We0[64 + tid], We0[96 + tid]);
    s->be0s[tid] = be0[tid];
  }
  __syncthreads();

  const int lane = tid & 31, wid = tid >> 5;
  const int q = lane & 3, g = lane >> 2;

  float* const gbuf = s->gbuf[wid];
  const float4* const Sg4 = reinterpret_cast<const float4*>(Sg);
  const float4* const R4 = reinterpret_cast<const float4*>(R);

  for (int it = blockIdx.x * WARPS1 + wid; it < NPAIR2; it += GRID1 * WARPS1) {
    const int pair0 = it * 2;
    float bm[2][4] = {{0.f, 0.f, 0.f, 0.f}, {0.f, 0.f, 0.f, 0.f}};

#pragma unroll 1
    for (int pp = 0; pp < 2; pp++) {
      const float4* const sgb = Sg4 + (pair0 + pp) * Mm;

      unsigned a1h[2][2][4], a1l[2][2][4];
#pragma unroll
      for (int mt = 0; mt < 2; mt++) {
        int rA = mt * 16 + g;
        int rB = rA + 8;
        float4 sgA = sgb[rA];
        float4 sgB = (rB < Mm) ? sgb[rB] : make_float4(0.f, 0.f, 0.f, 0.f);
#pragma unroll
        for (int u = 0; u < 2; u++) {
          int c0 = u * 16 + 2 * q;
          int c2 = c0 + 8;
          float4 w0v = s->w0colf4[c0];
          float4 w1v = s->w0colf4[c0 + 1];
          float4 w2v = s->w0colf4[c2];
          float4 w3v = s->w0colf4[c2 + 1];
          float b0v = s->be0s[c0], b1v = s->be0s[c0 + 1];
          float b2v = s->be0s[c2], b3v = s->be0s[c2 + 1];
          bfsplit2(sigmoid_fast(b0v + dot4(sgA, w0v)),
                   sigmoid_fast(b1v + dot4(sgA, w1v)), a1h[mt][u][0],
                   a1l[mt][u][0]);
          bfsplit2(sigmoid_fast(b0v + dot4(sgB, w0v)),
                   sigmoid_fast(b1v + dot4(sgB, w1v)), a1h[mt][u][1],
                   a1l[mt][u][1]);
          bfsplit2(sigmoid_fast(b2v + dot4(sgA, w2v)),
                   sigmoid_fast(b3v + dot4(sgA, w3v)), a1h[mt][u][2],
                   a1l[mt][u][2]);
          bfsplit2(sigmoid_fast(b2v + dot4(sgB, w2v)),
                   sigmoid_fast(b3v + dot4(sgB, w3v)), a1h[mt][u][3],
                   a1l[mt][u][3]);
        }
      }

      float c1v[2][4][4];
#pragma unroll
      for (int nt = 0; nt < 4; nt++) {
        float2 bi = s->bias1f[nt * 32 + lane];
#pragma unroll
        for (int mt = 0; mt < 2; mt++) {
          c1v[mt][nt][0] = bi.x;
          c1v[mt][nt][1] = bi.y;
          c1v[mt][nt][2] = bi.x;
          c1v[mt][nt][3] = bi.y;
        }
#pragma unroll
        for (int u = 0; u < 2; u++) {
          uint4 bf = s->b1f[(u * 4 + nt) * 32 + lane];
#pragma unroll
          for (int mt = 0; mt < 2; mt++)
            mma3(c1v[mt][nt], a1h[mt][u], a1l[mt][u], bf);
        }
      }

      unsigned a2h[2][2][4], a2l[2][2][4];
#pragma unroll
      for (int mt = 0; mt < 2; mt++) {
#pragma unroll
        for (int nt = 0; nt < 4; nt++)
#pragma unroll
          for (int j = 0; j < 4; j++)
            c1v[mt][nt][j] = tanh_fast(c1v[mt][nt][j]);
#pragma unroll
        for (int u = 0; u < 2; u++)
          c2a_pack(c1v[mt][2 * u], c1v[mt][2 * u + 1], a2h[mt][u], a2l[mt][u]);
      }

      float c2v[2][4][4];
#pragma unroll
      for (int nt = 0; nt < 4; nt++) {
        float2 bi = s->bias2f[nt * 32 + lane];
#pragma unroll
        for (int mt = 0; mt < 2; mt++) {
          c2v[mt][nt][0] = bi.x;
          c2v[mt][nt][1] = bi.y;
          c2v[mt][nt][2] = bi.x;
          c2v[mt][nt][3] = bi.y;
        }
#pragma unroll
        for (int u = 0; u < 2; u++) {
          uint4 bf = s->b2f[(u * 4 + nt) * 32 + lane];
#pragma unroll
          for (int mt = 0; mt < 2; mt++)
            mma3(c2v[mt][nt], a2h[mt][u], a2l[mt][u], bf);
        }
      }

#pragma unroll
      for (int mt = 0; mt < 2; mt++) {
#pragma unroll
        for (int nt = 0; nt < 4; nt++) {
          int colb = nt * 8 + 2 * q;
          int r0r = mt * 16 + g;
          *reinterpret_cast<float2*>(&gbuf[r0r * GSTRIDE + colb]) =
              make_float2(c2v[mt][nt][0], c2v[mt][nt][1]);
          int r1r = r0r + 8;
          if (r1r < Mm)
            *reinterpret_cast<float2*>(&gbuf[r1r * GSTRIDE + colb]) =
                make_float2(c2v[mt][nt][2], c2v[mt][nt][3]);
        }
      }
      __syncwarp();
      const float4* const rb = R4 + (pair0 + pp) * Mm;
#pragma unroll 6
      for (int m = 0; m < Mm; m++) {
        float gv = gbuf[m * GSTRIDE + lane];
        float4 r = rb[m];
        bm[pp][0] += r.x * gv;
        bm[pp][1] += r.y * gv;
        bm[pp][2] += r.z * gv;
        bm[pp][3] += r.w * gv;
      }
      __syncwarp();
    }

#pragma unroll
    for (int pp = 0; pp < 2; pp++) {
      float d[8];
#pragma unroll
      for (int k = 0; k < 8; k++) {
        float dv = 0.f;
#pragma unroll
        for (int l = 0; l < 4; l++) {
          float a = __shfl_sync(FULLM, bm[pp][l], k);
          dv += a * bm[pp][l];
        }
        d[k] = dv;
      }
      unsigned h[4], lo[4];
#pragma unroll
      for (int t2 = 0; t2 < 4; t2++)
        bfsplit2(d[2 * t2], d[2 * t2 + 1], h[t2], lo[t2]);
      uint4* dst = reinterpret_cast<uint4*>(
          Dg2 + (size_t)(pair0 + pp) * 128 + lane * 4);
      dst[0] = make_uint4(h[0], lo[0], h[1], lo[1]);
      dst[1] = make_uint4(h[2], lo[2], h[3], lo[3]);
    }
  }
}

// ======================= Kernel 2: fit MLP (R13 best-measured) =============

__global__ void __launch_bounds__(THREADS2, 2) fit_kernel(
    float* __restrict__ out) {
  extern __shared__ char smraw[];
  Smem2* s = reinterpret_cast<Smem2*>(smraw);
  const int tid = threadIdx.x;

  for (int i = tid; i < 16 * 8 * 32; i += THREADS2) s->f0[i] = Gf0[i];
  for (int i = tid; i < 4 * 8 * 32; i += THREADS2) {
    s->f1[i] = Gf1[i];
    s->f2[i] = Gf2[i];
  }
  for (int i = tid; i < 256; i += THREADS2) {
    s->bias0f[i] = Gb0[i];
    s->bias1f[i] = Gb1[i];
    s->bias2f[i] = Gb2[i];
  }
  if (tid < 64) s->wf3s[tid] = Gw3[tid];
  if (tid == 0) s->bf3s = Gb3;
  __syncthreads();

  const int lane = tid & 31, wid = tid >> 5;
  const int q = lane & 3, g = lane >> 2;

  for (int t = blockIdx.x * WARPS2 + wid; t < NTILES; t += GRID2 * WARPS2) {
    const uint2* const dgp2 = Dg2 + (size_t)t * 16 * 128;

    float c0[8][4];
#pragma unroll
    for (int nt = 0; nt < 8; nt++) {
      float2 bi = s->bias0f[nt * 32 + lane];
      c0[nt][0] = bi.x;
      c0[nt][1] = bi.y;
      c0[nt][2] = bi.x;
      c0[nt][3] = bi.y;
    }
#pragma unroll 2
    for (int kt = 0; kt < 16; kt++) {
      const uint2* r0p = dgp2 + g * 128 + kt * 8;
      const uint2* r1p = dgp2 + (g + 8) * 128 + kt * 8;
      uint2 v0 = r0p[q];
      uint2 v1 = r1p[q];
      uint2 v2 = r0p[q + 4];
      uint2 v3 = r1p[q + 4];
      unsigned ah[4] = {v0.x, v1.x, v2.x, v3.x};
      unsigned al[4] = {v0.y, v1.y, v2.y, v3.y};
#pragma unroll
      for (int nt = 0; nt < 8; nt++)
        mma3(c0[nt], ah, al, s->f0[(kt * 8 + nt) * 32 + lane]);
    }
    unsigned ah1[4][4], al1[4][4];
#pragma unroll
    for (int nt = 0; nt < 8; nt++)
#pragma unroll
      for (int j = 0; j < 4; j++) c0[nt][j] = tanh_fast(c0[nt][j]);
#pragma unroll
    for (int u = 0; u < 4; u++)
      c2a_pack(c0[2 * u], c0[2 * u + 1], ah1[u], al1[u]);

    float c1[8][4];
#pragma unroll
    for (int nt = 0; nt < 8; nt++) {
      float2 bi = s->bias1f[nt * 32 + lane];
      c1[nt][0] = bi.x;
      c1[nt][1] = bi.y;
      c1[nt][2] = bi.x;
      c1[nt][3] = bi.y;
    }
#pragma unroll 2
    for (int kt = 0; kt < 4; kt++)
#pragma unroll
      for (int nt = 0; nt < 8; nt++)
        mma3(c1[nt], ah1[kt], al1[kt], s->f1[(kt * 8 + nt) * 32 + lane]);
#pragma unroll
    for (int nt = 0; nt < 8; nt++)
#pragma unroll
      for (int j = 0; j < 4; j++) c1[nt][j] = sigmoid_fast(c1[nt][j]);
#pragma unroll
    for (int u = 0; u < 4; u++)
      c2a_pack(c1[2 * u], c1[2 * u + 1], ah1[u], al1[u]);

    float c2[8][4];
#pragma unroll
    for (int nt = 0; nt < 8; nt++) {
      float2 bi = s->bias2f[nt * 32 + lane];
      c2[nt][0] = bi.x;
      c2[nt][1] = bi.y;
      c2[nt][2] = bi.x;
      c2[nt][3] = bi.y;
    }
#pragma unroll 2
    for (int kt = 0; kt < 4; kt++)
#pragma unroll
      for (int nt = 0; nt < 8; nt++)
        mma3(c2[nt], ah1[kt], al1[kt], s->f2[(kt * 8 + nt) * 32 + lane]);

    float slo = 0.f, shi = 0.f;
#pragma unroll
    for (int nt = 0; nt < 8; nt++) {
      float wa = s->wf3s[nt * 8 + 2 * q];
      float wb = s->wf3s[nt * 8 + 2 * q + 1];
      slo += tanh_fast(c2[nt][0]) * wa + tanh_fast(c2[nt][1]) * wb;
      shi += tanh_fast(c2[nt][2]) * wa + tanh_fast(c2[nt][3]) * wb;
    }
    float tot = slo + shi;
#pragma unroll
    for (int off = 16; off; off >>= 1) tot += __shfl_xor_sync(FULLM, tot, off);
    if (lane == 0) {
      atomicAdd(out + (t >> 5), (tot + 16.0f * s->bf3s) * (1.0f / 512.0f));
    }
  }
}

extern "C" void kernel_launch(void* const* d_in, const int* in_sizes, int n_in,
                              void* d_out, int out_size) {
  const float* Sg = (const float*)d_in[0];
  const float* R = (const float*)d_in[1];
  const float* We0 = (const float*)d_in[2];
  const float* be0 = (const float*)d_in[3];
  const float* We1 = (const float*)d_in[4];
  const float* be1 = (const float*)d_in[5];
  const float* We2 = (const float*)d_in[6];
  const float* be2 = (const float*)d_in[7];
  const float* Wf0 = (const float*)d_in[8];
  const float* bf0 = (const float*)d_in[9];
  const float* Wf1 = (const float*)d_in[10];
  const float* bf1 = (const float*)d_in[11];
  const float* Wf2 = (const float*)d_in[12];
  const float* bf2 = (const float*)d_in[13];
  const float* Wf3 = (const float*)d_in[14];
  const float* bf3 = (const float*)d_in[15];
  float* out = (float*)d_out;

  (void)in_sizes;
  (void)n_in;

  cudaFuncSetAttribute(emb_kernel, cudaFuncAttributeMaxDynamicSharedMemorySize,
                       (int)sizeof(Smem1));
  cudaFuncSetAttribute(fit_kernel, cudaFuncAttributeMaxDynamicSharedMemorySize,
                       (int)sizeof(Smem2));

  cudaMemsetAsync(out, 0, (size_t)out_size * sizeof(float));

  // Launch order: emb BEFORE setup (independent; stream serializes them
  // regardless). This places emb at launch position 2 of 4, so ncu's
  // "-s 5 -c 1" window (6th launch overall) captures EMB instead of fit.
  emb_kernel<<<GRID1, THREADS1, sizeof(Smem1)>>>(Sg, R, We0, be0, We1, be1,
                                                 We2, be2);
  setup_kernel<<<64, 128>>>(Wf0, bf0, Wf1, bf1, Wf2, bf2, Wf3, bf3);
  fit_kernel<<<GRID2, THREADS2, sizeof(Smem2)>>>(out);
}

// round 17
// speedup vs baseline: 1.0829x; 1.0612x over previous
#include <cuda_runtime.h>
#include <cstdint>

namespace {

constexpr int Mm = 30;
constexpr int NPAIR = 64 * 512;       // 32768
constexpr int NPAIR2 = NPAIR / 2;     // 16384 pair-pairs
constexpr unsigned FULLM = 0xffffffffu;
constexpr int GSTRIDE = 36;           // was 34: 4-way store conflicts -> 2-way

// emb kernel config
constexpr int WARPS1 = 8;
constexpr int THREADS1 = WARPS1 * 32;  // 256
constexpr int GRID1 = 296;             // 2 blocks/SM

// fit kernel config
constexpr int WARPS2 = 8;
constexpr int THREADS2 = WARPS2 * 32;  // 256
constexpr int GRID2 = 296;             // 2 blocks/SM
constexpr int NTILES = NPAIR / 16;     // 2048 (16 pairs per tile)

struct Smem1 {
  uint4  b1f[8 * 32];       // emb layer1 B-frags (b0h,b1h,b0l,b1l)
  uint4  b2f[8 * 32];
  float4 w0colf4[32];
  float2 bias1f[4 * 32];
  float2 bias2f[4 * 32];
  float  be0s[32];
  __align__(16) float gbuf[WARPS1][1088];  // 30*GSTRIDE = 1080
};

struct Smem2 {
  uint4  f0[16 * 8 * 32];   // fit0 B-frags, K-permuted by sigma  64 KB
  uint4  f1[4 * 8 * 32];    // 16 KB
  uint4  f2[4 * 8 * 32];    // 16 KB
  float2 bias0f[8 * 32];
  float2 bias1f[8 * 32];
  float2 bias2f[8 * 32];
  float  wf3s[64];
  float  bf3s;
};

// D scratch, pre-split bf16 hi/lo, K-permuted (R9/R13 layout): uint2 j =
// (hi,lo) bf16x2 of k' = 2j,2j+1 where k' = n*8 + k (sigma permutation).
__device__ uint2 Dg2[(size_t)NPAIR * 128];  // 32 MB (L2-resident when warm)

// Precomputed fit fragment tables (built once by setup_kernel).
__device__ uint4  Gf0[16 * 8 * 32];
__device__ uint4  Gf1[4 * 8 * 32];
__device__ uint4  Gf2[4 * 8 * 32];
__device__ float2 Gb0[8 * 32];
__device__ float2 Gb1[8 * 32];
__device__ float2 Gb2[8 * 32];
__device__ float  Gw3[64];
__device__ float  Gb3;

__host__ __device__ __forceinline__ int sigma(int r) {
  return (r & 7) * 32 + (r >> 3);
}

__device__ __forceinline__ float tanh_fast(float x) {
  float y;
  asm("tanh.approx.f32 %0, %1;" : "=f"(y) : "f"(x));
  return y;
}
__device__ __forceinline__ float sigmoid_fast(float x) {
  return 0.5f * tanh_fast(0.5f * x) + 0.5f;
}
__device__ __forceinline__ float dot4(float4 a, float4 b) {
  return a.x * b.x + a.y * b.y + a.z * b.z + a.w * b.w;
}
// streaming read (LDG.128.STRM): read-once inputs shouldn't evict Dg2/tables
__device__ __forceinline__ float4 ldg_stream4(const float4* p) {
  return __ldcs(p);
}
__device__ __forceinline__ unsigned bfpack(float keven, float kodd) {
  unsigned r;
  asm("cvt.rn.bf16x2.f32 %0, %1, %2;" : "=r"(r) : "f"(kodd), "f"(keven));
  return r;
}
__device__ __forceinline__ void bfsplit2(float x0, float x1, unsigned& h,
                                         unsigned& l) {
  h = bfpack(x0, x1);
  float h0 = __uint_as_float(h << 16);
  float h1 = __uint_as_float(h & 0xFFFF0000u);
  l = bfpack(x0 - h0, x1 - h1);
}
__device__ __forceinline__ void mma16(float c[4], const unsigned a[4],
                                      unsigned b0, unsigned b1) {
  asm volatile(
      "mma.sync.aligned.m16n8k16.row.col.f32.bf16.bf16.f32 "
      "{%0,%1,%2,%3}, {%4,%5,%6,%7}, {%8,%9}, {%0,%1,%2,%3};"
      : "+f"(c[0]), "+f"(c[1]), "+f"(c[2]), "+f"(c[3])
      : "r"(a[0]), "r"(a[1]), "r"(a[2]), "r"(a[3]), "r"(b0), "r"(b1));
}
__device__ __forceinline__ void mma3(float c[4], const unsigned ah[4],
                                     const unsigned al[4], uint4 bf) {
  mma16(c, ah, bf.x, bf.y);
  mma16(c, al, bf.x, bf.y);
  mma16(c, ah, bf.z, bf.w);
}
__device__ __forceinline__ void c2a_pack(const float ce[4], const float co[4],
                                         unsigned ah[4], unsigned al[4]) {
  bfsplit2(ce[0], ce[1], ah[0], al[0]);
  bfsplit2(ce[2], ce[3], ah[1], al[1]);
  bfsplit2(co[0], co[1], ah[2], al[2]);
  bfsplit2(co[2], co[3], ah[3], al[3]);
}

}  // namespace

// ======================= Kernel 0: one-shot fragment-table build ===========

__global__ void setup_kernel(const float* __restrict__ Wf0,
                             const float* __restrict__ bf0,
                             const float* __restrict__ Wf1,
                             const float* __restrict__ bf1,
                             const float* __restrict__ Wf2,
                             const float* __restrict__ bf2,
                             const float* __restrict__ Wf3,
                             const float* __restrict__ bf3) {
  const int gt = blockIdx.x * blockDim.x + threadIdx.x;
  const int nthr = gridDim.x * blockDim.x;
  for (int i = gt; i < 16 * 8 * 32; i += nthr) {
    int L = i & 31, nt = (i >> 5) & 7, kt = i >> 8;
    int q = L & 3, g = L >> 2;
    int r00 = kt * 16 + 2 * q, r10 = r00 + 8;
    int c = nt * 8 + g;
    unsigned b0h, b0l, b1h, b1l;
    bfsplit2(Wf0[sigma(r00) * 64 + c], Wf0[sigma(r00 + 1) * 64 + c], b0h, b0l);
    bfsplit2(Wf0[sigma(r10) * 64 + c], Wf0[sigma(r10 + 1) * 64 + c], b1h, b1l);
    Gf0[i] = make_uint4(b0h, b1h, b0l, b1l);
  }
  for (int i = gt; i < 4 * 8 * 32; i += nthr) {
    int L = i & 31, nt = (i >> 5) & 7, kt = i >> 8;
    int q = L & 3, g = L >> 2;
    int r00 = kt * 16 + 2 * q, r10 = r00 + 8;
    int c = nt * 8 + g;
    unsigned b0h, b0l, b1h, b1l;
    bfsplit2(Wf1[r00 * 64 + c], Wf1[(r00 + 1) * 64 + c], b0h, b0l);
    bfsplit2(Wf1[r10 * 64 + c], Wf1[(r10 + 1) * 64 + c], b1h, b1l);
    Gf1[i] = make_uint4(b0h, b1h, b0l, b1l);
    bfsplit2(Wf2[r00 * 64 + c], Wf2[(r00 + 1) * 64 + c], b0h, b0l);
    bfsplit2(Wf2[r10 * 64 + c], Wf2[(r10 + 1) * 64 + c], b1h, b1l);
    Gf2[i] = make_uint4(b0h, b1h, b0l, b1l);
  }
  for (int i = gt; i < 256; i += nthr) {
    int nt = i >> 5, q = i & 3;
    Gb0[i] = make_float2(bf0[nt * 8 + 2 * q], bf0[nt * 8 + 2 * q + 1]);
    Gb1[i] = make_float2(bf1[nt * 8 + 2 * q], bf1[nt * 8 + 2 * q + 1]);
    Gb2[i] = make_float2(bf2[nt * 8 + 2 * q], bf2[nt * 8 + 2 * q + 1]);
  }
  if (gt < 64) Gw3[gt] = Wf3[gt];
  if (gt == 0) Gb3 = bf3[0];
}

// ======================= Kernel 1: emb MLP + bilinear -> D =================

__global__ void __launch_bounds__(THREADS1, 2) emb_kernel(
    const float* __restrict__ Sg, const float* __restrict__ R,
    const float* __restrict__ We0, const float* __restrict__ be0,
    const float* __restrict__ We1, const float* __restrict__ be1,
    const float* __restrict__ We2, const float* __restrict__ be2) {
  extern __shared__ char smraw[];
  Smem1* s = reinterpret_cast<Smem1*>(smraw);
  const int tid = threadIdx.x;

  for (int i = tid; i < 256; i += THREADS1) {
    int L = i & 31, nt = (i >> 5) & 3, u = i >> 7;
    int q = L & 3, g = L >> 2;
    int r00 = u * 16 + 2 * q, r10 = r00 + 8;
    int c = nt * 8 + g;
    unsigned b0h, b0l, b1h, b1l;
    bfsplit2(We1[r00 * 32 + c], We1[(r00 + 1) * 32 + c], b0h, b0l);
    bfsplit2(We1[r10 * 32 + c], We1[(r10 + 1) * 32 + c], b1h, b1l);
    s->b1f[i] = make_uint4(b0h, b1h, b0l, b1l);
    bfsplit2(We2[r00 * 32 + c], We2[(r00 + 1) * 32 + c], b0h, b0l);
    bfsplit2(We2[r10 * 32 + c], We2[(r10 + 1) * 32 + c], b1h, b1l);
    s->b2f[i] = make_uint4(b0h, b1h, b0l, b1l);
  }
  for (int i = tid; i < 128; i += THREADS1) {
    int t = i >> 5, L = i & 31, q = L & 3;
    s->bias1f[i] = make_float2(be1[t * 8 + 2 * q], be1[t * 8 + 2 * q + 1]);
    s->bias2f[i] = make_float2(be2[t * 8 + 2 * q], be2[t * 8 + 2 * q + 1]);
  }
  if (tid < 32) {
    s->w0colf4[tid] =
        make_float4(We0[tid], We0[32 + tid], We0[64 + tid], We0[96 + tid]);
    s->be0s[tid] = be0[tid];
  }
  __syncthreads();

  const int lane = tid & 31, wid = tid >> 5;
  const int q = lane & 3, g = lane >> 2;

  float* const gbuf = s->gbuf[wid];
  const float4* const Sg4 = reinterpret_cast<const float4*>(Sg);
  const float4* const R4 = reinterpret_cast<const float4*>(R);

  for (int it = blockIdx.x * WARPS1 + wid; it < NPAIR2; it += GRID1 * WARPS1) {
    const int pair0 = it * 2;
    float bm[2][4] = {{0.f, 0.f, 0.f, 0.f}, {0.f, 0.f, 0.f, 0.f}};

#pragma unroll 1
    for (int pp = 0; pp < 2; pp++) {
      const float4* const sgb = Sg4 + (pair0 + pp) * Mm;

      unsigned a1h[2][2][4], a1l[2][2][4];
#pragma unroll
      for (int mt = 0; mt < 2; mt++) {
        int rA = mt * 16 + g;
        int rB = rA + 8;
        float4 sgA = ldg_stream4(sgb + rA);
        float4 sgB =
            (rB < Mm) ? ldg_stream4(sgb + rB) : make_float4(0.f, 0.f, 0.f, 0.f);
#pragma unroll
        for (int u = 0; u < 2; u++) {
          int c0 = u * 16 + 2 * q;
          int c2 = c0 + 8;
          float4 w0v = s->w0colf4[c0];
          float4 w1v = s->w0colf4[c0 + 1];
          float4 w2v = s->w0colf4[c2];
          float4 w3v = s->w0colf4[c2 + 1];
          float b0v = s->be0s[c0], b1v = s->be0s[c0 + 1];
          float b2v = s->be0s[c2], b3v = s->be0s[c2 + 1];
          bfsplit2(sigmoid_fast(b0v + dot4(sgA, w0v)),
                   sigmoid_fast(b1v + dot4(sgA, w1v)), a1h[mt][u][0],
                   a1l[mt][u][0]);
          bfsplit2(sigmoid_fast(b0v + dot4(sgB, w0v)),
                   sigmoid_fast(b1v + dot4(sgB, w1v)), a1h[mt][u][1],
                   a1l[mt][u][1]);
          bfsplit2(sigmoid_fast(b2v + dot4(sgA, w2v)),
                   sigmoid_fast(b3v + dot4(sgA, w3v)), a1h[mt][u][2],
                   a1l[mt][u][2]);
          bfsplit2(sigmoid_fast(b2v + dot4(sgB, w2v)),
                   sigmoid_fast(b3v + dot4(sgB, w3v)), a1h[mt][u][3],
                   a1l[mt][u][3]);
        }
      }

      float c1v[2][4][4];
#pragma unroll
      for (int nt = 0; nt < 4; nt++) {
        float2 bi = s->bias1f[nt * 32 + lane];
#pragma unroll
        for (int mt = 0; mt < 2; mt++) {
          c1v[mt][nt][0] = bi.x;
          c1v[mt][nt][1] = bi.y;
          c1v[mt][nt][2] = bi.x;
          c1v[mt][nt][3] = bi.y;
        }
#pragma unroll
        for (int u = 0; u < 2; u++) {
          uint4 bf = s->b1f[(u * 4 + nt) * 32 + lane];
#pragma unroll
          for (int mt = 0; mt < 2; mt++)
            mma3(c1v[mt][nt], a1h[mt][u], a1l[mt][u], bf);
        }
      }

      unsigned a2h[2][2][4], a2l[2][2][4];
#pragma unroll
      for (int mt = 0; mt < 2; mt++) {
#pragma unroll
        for (int nt = 0; nt < 4; nt++)
#pragma unroll
          for (int j = 0; j < 4; j++)
            c1v[mt][nt][j] = tanh_fast(c1v[mt][nt][j]);
#pragma unroll
        for (int u = 0; u < 2; u++)
          c2a_pack(c1v[mt][2 * u], c1v[mt][2 * u + 1], a2h[mt][u], a2l[mt][u]);
      }

      float c2v[2][4][4];
#pragma unroll
      for (int nt = 0; nt < 4; nt++) {
        float2 bi = s->bias2f[nt * 32 + lane];
#pragma unroll
        for (int mt = 0; mt < 2; mt++) {
          c2v[mt][nt][0] = bi.x;
          c2v[mt][nt][1] = bi.y;
          c2v[mt][nt][2] = bi.x;
          c2v[mt][nt][3] = bi.y;
        }
#pragma unroll
        for (int u = 0; u < 2; u++) {
          uint4 bf = s->b2f[(u * 4 + nt) * 32 + lane];
#pragma unroll
          for (int mt = 0; mt < 2; mt++)
            mma3(c2v[mt][nt], a2h[mt][u], a2l[mt][u], bf);
        }
      }

#pragma unroll
      for (int mt = 0; mt < 2; mt++) {
#pragma unroll
        for (int nt = 0; nt < 4; nt++) {
          int colb = nt * 8 + 2 * q;
          int r0r = mt * 16 + g;
          *reinterpret_cast<float2*>(&gbuf[r0r * GSTRIDE + colb]) =
              make_float2(c2v[mt][nt][0], c2v[mt][nt][1]);
          int r1r = r0r + 8;
          if (r1r < Mm)
            *reinterpret_cast<float2*>(&gbuf[r1r * GSTRIDE + colb]) =
                make_float2(c2v[mt][nt][2], c2v[mt][nt][3]);
        }
      }
      __syncwarp();
      const float4* const rb = R4 + (pair0 + pp) * Mm;
#pragma unroll 6
      for (int m = 0; m < Mm; m++) {
        float gv = gbuf[m * GSTRIDE + lane];
        float4 r = ldg_stream4(rb + m);
        bm[pp][0] += r.x * gv;
        bm[pp][1] += r.y * gv;
        bm[pp][2] += r.z * gv;
        bm[pp][3] += r.w * gv;
      }
      __syncwarp();
    }

#pragma unroll
    for (int pp = 0; pp < 2; pp++) {
      float d[8];
#pragma unroll
      for (int k = 0; k < 8; k++) {
        float dv = 0.f;
#pragma unroll
        for (int l = 0; l < 4; l++) {
          float a = __shfl_sync(FULLM, bm[pp][l], k);
          dv += a * bm[pp][l];
        }
        d[k] = dv;
      }
      unsigned h[4], lo[4];
#pragma unroll
      for (int t2 = 0; t2 < 4; t2++)
        bfsplit2(d[2 * t2], d[2 * t2 + 1], h[t2], lo[t2]);
      uint4* dst = reinterpret_cast<uint4*>(
          Dg2 + (size_t)(pair0 + pp) * 128 + lane * 4);
      dst[0] = make_uint4(h[0], lo[0], h[1], lo[1]);
      dst[1] = make_uint4(h[2], lo[2], h[3], lo[3]);
    }
  }
}

// ======================= Kernel 2: fit MLP (R13 best-measured) =============

__global__ void __launch_bounds__(THREADS2, 2) fit_kernel(
    float* __restrict__ out) {
  extern __shared__ char smraw[];
  Smem2* s = reinterpret_cast<Smem2*>(smraw);
  const int tid = threadIdx.x;

  for (int i = tid; i < 16 * 8 * 32; i += THREADS2) s->f0[i] = Gf0[i];
  for (int i = tid; i < 4 * 8 * 32; i += THREADS2) {
    s->f1[i] = Gf1[i];
    s->f2[i] = Gf2[i];
  }
  for (int i = tid; i < 256; i += THREADS2) {
    s->bias0f[i] = Gb0[i];
    s->bias1f[i] = Gb1[i];
    s->bias2f[i] = Gb2[i];
  }
  if (tid < 64) s->wf3s[tid] = Gw3[tid];
  if (tid == 0) s->bf3s = Gb3;
  __syncthreads();

  const int lane = tid & 31, wid = tid >> 5;
  const int q = lane & 3, g = lane >> 2;

  for (int t = blockIdx.x * WARPS2 + wid; t < NTILES; t += GRID2 * WARPS2) {
    const uint2* const dgp2 = Dg2 + (size_t)t * 16 * 128;

    float c0[8][4];
#pragma unroll
    for (int nt = 0; nt < 8; nt++) {
      float2 bi = s->bias0f[nt * 32 + lane];
      c0[nt][0] = bi.x;
      c0[nt][1] = bi.y;
      c0[nt][2] = bi.x;
      c0[nt][3] = bi.y;
    }
#pragma unroll 4
    for (int kt = 0; kt < 16; kt++) {
      const uint2* r0p = dgp2 + g * 128 + kt * 8;
      const uint2* r1p = dgp2 + (g + 8) * 128 + kt * 8;
      uint2 v0 = r0p[q];
      uint2 v1 = r1p[q];
      uint2 v2 = r0p[q + 4];
      uint2 v3 = r1p[q + 4];
      unsigned ah[4] = {v0.x, v1.x, v2.x, v3.x};
      unsigned al[4] = {v0.y, v1.y, v2.y, v3.y};
#pragma unroll
      for (int nt = 0; nt < 8; nt++)
        mma3(c0[nt], ah, al, s->f0[(kt * 8 + nt) * 32 + lane]);
    }
    unsigned ah1[4][4], al1[4][4];
#pragma unroll
    for (int nt = 0; nt < 8; nt++)
#pragma unroll
      for (int j = 0; j < 4; j++) c0[nt][j] = tanh_fast(c0[nt][j]);
#pragma unroll
    for (int u = 0; u < 4; u++)
      c2a_pack(c0[2 * u], c0[2 * u + 1], ah1[u], al1[u]);

    float c1[8][4];
#pragma unroll
    for (int nt = 0; nt < 8; nt++) {
      float2 bi = s->bias1f[nt * 32 + lane];
      c1[nt][0] = bi.x;
      c1[nt][1] = bi.y;
      c1[nt][2] = bi.x;
      c1[nt][3] = bi.y;
    }
#pragma unroll 2
    for (int kt = 0; kt < 4; kt++)
#pragma unroll
      for (int nt = 0; nt < 8; nt++)
        mma3(c1[nt], ah1[kt], al1[kt], s->f1[(kt * 8 + nt) * 32 + lane]);
#pragma unroll
    for (int nt = 0; nt < 8; nt++)
#pragma unroll
      for (int j = 0; j < 4; j++) c1[nt][j] = sigmoid_fast(c1[nt][j]);
#pragma unroll
    for (int u = 0; u < 4; u++)
      c2a_pack(c1[2 * u], c1[2 * u + 1], ah1[u], al1[u]);

    float c2[8][4];
#pragma unroll
    for (int nt = 0; nt < 8; nt++) {
      float2 bi = s->bias2f[nt * 32 + lane];
      c2[nt][0] = bi.x;
      c2[nt][1] = bi.y;
      c2[nt][2] = bi.x;
      c2[nt][3] = bi.y;
    }
#pragma unroll 2
    for (int kt = 0; kt < 4; kt++)
#pragma unroll
      for (int nt = 0; nt < 8; nt++)
        mma3(c2[nt], ah1[kt], al1[kt], s->f2[(kt * 8 + nt) * 32 + lane]);

    float slo = 0.f, shi = 0.f;
#pragma unroll
    for (int nt = 0; nt < 8; nt++) {
      float wa = s->wf3s[nt * 8 + 2 * q];
      float wb = s->wf3s[nt * 8 + 2 * q + 1];
      slo += tanh_fast(c2[nt][0]) * wa + tanh_fast(c2[nt][1]) * wb;
      shi += tanh_fast(c2[nt][2]) * wa + tanh_fast(c2[nt][3]) * wb;
    }
    float tot = slo + shi;
#pragma unroll
    for (int off = 16; off; off >>= 1) tot += __shfl_xor_sync(FULLM, tot, off);
    if (lane == 0) {
      atomicAdd(out + (t >> 5), (tot + 16.0f * s->bf3s) * (1.0f / 512.0f));
    }
  }
}

extern "C" void kernel_launch(void* const* d_in, const int* in_sizes, int n_in,
                              void* d_out, int out_size) {
  const float* Sg = (const float*)d_in[0];
  const float* R = (const float*)d_in[1];
  const float* We0 = (const float*)d_in[2];
  const float* be0 = (const float*)d_in[3];
  const float* We1 = (const float*)d_in[4];
  const float* be1 = (const float*)d_in[5];
  const float* We2 = (const float*)d_in[6];
  const float* be2 = (const float*)d_in[7];
  const float* Wf0 = (const float*)d_in[8];
  const float* bf0 = (const float*)d_in[9];
  const float* Wf1 = (const float*)d_in[10];
  const float* bf1 = (const float*)d_in[11];
  const float* Wf2 = (const float*)d_in[12];
  const float* bf2 = (const float*)d_in[13];
  const float* Wf3 = (const float*)d_in[14];
  const float* bf3 = (const float*)d_in[15];
  float* out = (float*)d_out;

  (void)in_sizes;
  (void)n_in;

  cudaFuncSetAttribute(emb_kernel, cudaFuncAttributeMaxDynamicSharedMemorySize,
                       (int)sizeof(Smem1));
  cudaFuncSetAttribute(fit_kernel, cudaFuncAttributeMaxDynamicSharedMemorySize,
                       (int)sizeof(Smem2));

  cudaMemsetAsync(out, 0, (size_t)out_size * sizeof(float));

  // emb first (keeps emb in ncu's sample window), then setup, then fit.
  emb_kernel<<<GRID1, THREADS1, sizeof(Smem1)>>>(Sg, R, We0, be0, We1, be1,
                                                 We2, be2);
  setup_kernel<<<64, 128>>>(Wf0, bf0, Wf1, bf1, Wf2, bf2, Wf3, bf3);
  fit_kernel<<<GRID2, THREADS2, sizeof(Smem2)>>>(out);
}